// round 8
// baseline (speedup 1.0000x reference)
#include <cuda_runtime.h>
#include <math.h>

#define BB 4
#define NN 512
#define DD 128
#define TAU_INV 2.0f
#define EPSF 1e-9f

#define TI 16            // i rows per k_main block
#define JS 4             // j splits
#define JR (NN/JS)       // 128 j's per block
#define TJ 32            // j tile staged in shared

// k_proj tiles
#define PBM 32
#define PBN 64
#define PBK 32
#define APAD 2

// k_epi
#define ERM 8            // rows per k_epi block

// ---------------- scratch ----------------
__device__ float g_sj[BB * NN * DD];          // (ES@Wp+bp)@W1_src + Bc_s
__device__ float g_ti[BB * NN * DD];          // (ES@Wp+bp)@W1_tgt + Bc_t (b1 folded)
__device__ float g_v [JS * BB * NN * DD];     // partial v per j-split (4 MB)
__device__ float g_Wc[DD * 256];              // combined weights [d][col], col<128 src
__device__ float g_Bc[256];                   // combined bias
__device__ __align__(16) float g_W2p[DD * DD];// pair-transposed W2: float2[mp][k]

// ---------------- packed f32x2 helpers ----------------
__device__ __forceinline__ void fma2acc(unsigned long long& acc,
                                        unsigned long long a, unsigned long long b) {
    asm("fma.rn.f32x2 %0, %1, %2, %0;" : "+l"(acc) : "l"(a), "l"(b));
}
__device__ __forceinline__ unsigned long long bcast2(float a) {
    unsigned long long r;
    asm("mov.b64 %0, {%1, %1};" : "=l"(r) : "f"(a));
    return r;
}
__device__ __forceinline__ float2 unpack2(unsigned long long v) {
    float2 r;
    asm("mov.b64 {%0, %1}, %2;" : "=f"(r.x), "=f"(r.y) : "l"(v));
    return r;
}
// acc += a * relu(s + t), 4 lanes (2 b64 packs)
__device__ __forceinline__ void relu_mad4(unsigned long long& acc0, unsigned long long& acc1,
                                          unsigned long long s0, unsigned long long s1,
                                          unsigned long long t0, unsigned long long t1,
                                          unsigned long long a2)
{
    asm("{\n\t"
        ".reg .b64 x0, x1;\n\t"
        ".reg .f32 l0, h0, l1, h1;\n\t"
        "add.rn.f32x2 x0, %2, %4;\n\t"
        "add.rn.f32x2 x1, %3, %5;\n\t"
        "mov.b64 {l0, h0}, x0;\n\t"
        "mov.b64 {l1, h1}, x1;\n\t"
        "max.f32 l0, l0, 0f00000000;\n\t"
        "max.f32 h0, h0, 0f00000000;\n\t"
        "max.f32 l1, l1, 0f00000000;\n\t"
        "max.f32 h1, h1, 0f00000000;\n\t"
        "mov.b64 x0, {l0, h0};\n\t"
        "mov.b64 x1, {l1, h1};\n\t"
        "fma.rn.f32x2 %0, x0, %6, %0;\n\t"
        "fma.rn.f32x2 %1, x1, %6, %1;\n\t"
        "}"
        : "+l"(acc0), "+l"(acc1)
        : "l"(s0), "l"(s1), "l"(t0), "l"(t1), "l"(a2));
}

// ============ K0: Wc = Wp @ [W1s|W1t]; Bc; W2 pair-transpose ============
// grid DD+17: blocks 0..127 weights, 128 biases, 129..144 W2 pack.
__global__ void __launch_bounds__(256) k_combine(const float* __restrict__ Wp,
                                                 const float* __restrict__ bp,
                                                 const float* __restrict__ W1,
                                                 const float* __restrict__ b1,
                                                 const float* __restrict__ W2)
{
    __shared__ float wp[DD];
    int col  = threadIdx.x;          // 0..255
    int d    = blockIdx.x;
    int half = col >> 7;
    int m    = col & 127;
    const float* base = W1 + (size_t)(half ? DD * DD : 0) + m;

    if (d < DD) {
        if (col < DD) wp[col] = Wp[d * DD + col];
        __syncthreads();
        float acc = 0.f;
        #pragma unroll 8
        for (int k = 0; k < DD; k++) acc += wp[k] * base[(size_t)k * DD];
        g_Wc[d * 256 + col] = acc;
    } else if (d == DD) {
        float acc = half ? b1[m] : 0.f;
        #pragma unroll 8
        for (int k = 0; k < DD; k++) acc += bp[k] * base[(size_t)k * DD];
        g_Bc[col] = acc;
    } else {
        // W2 pair pack: g_W2p[mp][k] = (W2[k][2mp], W2[k][2mp+1]); 8192 float2 total
        int t = (d - DD - 1) * 256 + col;   // 0..4095
        float2* W2P = (float2*)g_W2p;
        #pragma unroll
        for (int q = 0; q < 2; q++) {
            int p  = t * 2 + q;             // 0..8191
            int mp = p >> 7;
            int k  = p & 127;
            W2P[p] = make_float2(W2[k * DD + 2 * mp], W2[k * DD + 2 * mp + 1]);
        }
    }
}

// ============ K1: tiled GEMM: [s|t] = ES @ Wc + Bc ============
__global__ void __launch_bounds__(256) k_proj(const float* __restrict__ ES)
{
    __shared__ float sE[PBK][PBM + APAD];   // transposed: sE[k][row]
    __shared__ float sW[PBK][PBN];

    int tid = threadIdx.x;
    int tx  = tid & 15;
    int ty  = tid >> 4;
    int r0  = blockIdx.x * PBM;
    int c0  = blockIdx.y * PBN;

    int lrow = tid >> 3;
    int lk4  = tid & 7;
    int wk   = tid >> 4;
    int wc4  = tid & 15;

    float4 eA, wB[2];
    {
        eA    = *(const float4*)&ES[(size_t)(r0 + lrow) * DD + lk4 * 4];
        const float* wpg = g_Wc + c0;
        wB[0] = *(const float4*)&wpg[(wk     ) * 256 + wc4 * 4];
        wB[1] = *(const float4*)&wpg[(wk + 16) * 256 + wc4 * 4];
    }

    unsigned long long acc[2][2];
    acc[0][0] = acc[0][1] = acc[1][0] = acc[1][1] = 0ull;

    for (int kt = 0; kt < DD; kt += PBK) {
        if (kt) __syncthreads();
        sE[lk4 * 4 + 0][lrow] = eA.x;
        sE[lk4 * 4 + 1][lrow] = eA.y;
        sE[lk4 * 4 + 2][lrow] = eA.z;
        sE[lk4 * 4 + 3][lrow] = eA.w;
        *(float4*)&sW[wk][wc4 * 4]      = wB[0];
        *(float4*)&sW[wk + 16][wc4 * 4] = wB[1];
        __syncthreads();

        if (kt + PBK < DD) {
            eA    = *(const float4*)&ES[(size_t)(r0 + lrow) * DD + (kt + PBK) + lk4 * 4];
            const float* wpg = g_Wc + c0 + (size_t)(kt + PBK) * 256;
            wB[0] = *(const float4*)&wpg[(wk     ) * 256 + wc4 * 4];
            wB[1] = *(const float4*)&wpg[(wk + 16) * 256 + wc4 * 4];
        }

        #pragma unroll 8
        for (int k = 0; k < PBK; k++) {
            float2 e2 = *(const float2*)&sE[k][ty * 2];
            ulonglong2 w2 = *(const ulonglong2*)&sW[k][tx * 4];
            unsigned long long e0 = bcast2(e2.x);
            unsigned long long e1 = bcast2(e2.y);
            fma2acc(acc[0][0], e0, w2.x); fma2acc(acc[0][1], e0, w2.y);
            fma2acc(acc[1][0], e1, w2.x); fma2acc(acc[1][1], e1, w2.y);
        }
    }

    float4 bias = *(const float4*)&g_Bc[c0 + tx * 4];
    float* dst = (c0 < DD) ? g_sj : g_ti;
    int    mc  = (c0 < DD) ? c0 : (c0 - DD);
    #pragma unroll
    for (int r = 0; r < 2; r++) {
        int row = r0 + ty * 2 + r;
        float2 p0 = unpack2(acc[r][0]);
        float2 p1 = unpack2(acc[r][1]);
        float4 o;
        o.x = p0.x + bias.x; o.y = p0.y + bias.y;
        o.z = p1.x + bias.z; o.w = p1.y + bias.w;
        *(float4*)&dst[(size_t)row * DD + mc + tx * 4] = o;
    }
}

// ============ K2: fused gumbel-softmax + partial message aggregation ============
__global__ void __launch_bounds__(256, 4) k_main(const float* __restrict__ EL,
                                                 const float* __restrict__ UN,
                                                 float* __restrict__ out_A)
{
    __shared__ float sA[TI * JR];    // 8 KB
    __shared__ float sS[TJ * DD];    // 16 KB

    int tid = threadIdx.x;
    int b   = blockIdx.y;
    int i0  = blockIdx.x * TI;
    int js  = blockIdx.z;

    // phase A: gumbel-softmax rows i0..i0+15
    {
        int warp = tid >> 5, lane = tid & 31;
        #pragma unroll
        for (int rr = 0; rr < 2; rr++) {
            int r = warp * 2 + rr;
            int i = i0 + r;
            const float* elp = EL + (size_t)i * NN;
            const float* up  = UN + (size_t)i * NN;
            float xv[16];
            float mx = -1e30f;
            #pragma unroll
            for (int c = 0; c < 16; c++) {
                int j = c * 32 + lane;
                float inner = logf(up[j] + EPSF);
                float g = -__logf(-inner + EPSF);
                float x = (elp[j] + g) * TAU_INV;
                xv[c] = x;
                mx = fmaxf(mx, x);
            }
            #pragma unroll
            for (int o = 16; o > 0; o >>= 1) mx = fmaxf(mx, __shfl_xor_sync(0xffffffffu, mx, o));
            float s = 0.f;
            #pragma unroll
            for (int c = 0; c < 16; c++) { float e = __expf(xv[c] - mx); xv[c] = e; s += e; }
            #pragma unroll
            for (int o = 16; o > 0; o >>= 1) s += __shfl_xor_sync(0xffffffffu, s, o);
            float rinv = 1.0f / s;
            float* oA = out_A + ((size_t)b * NN + i) * NN;
            #pragma unroll
            for (int c = 0; c < 16; c++) {
                float a = xv[c] * rinv;
                if ((c >> 2) == js) sA[r * JR + (c & 3) * 32 + lane] = a;
                if (js == 0) oA[c * 32 + lane] = a;
            }
        }
    }
    __syncthreads();

    // phase B
    int kq = tid & 31;
    int ig = tid >> 5;
    int iA = ig * 2, iB = ig * 2 + 1;

    ulonglong2 tA = *(const ulonglong2*)&g_ti[((size_t)(b * NN + i0 + iA)) * DD + kq * 4];
    ulonglong2 tB = *(const ulonglong2*)&g_ti[((size_t)(b * NN + i0 + iB)) * DD + kq * 4];
    unsigned long long accA0 = 0ull, accA1 = 0ull, accB0 = 0ull, accB1 = 0ull;

    const float4* sb4 = (const float4*)(g_sj + ((size_t)b * NN + js * JR) * DD);

    #pragma unroll 1
    for (int t = 0; t < JR / TJ; t++) {
        #pragma unroll
        for (int q = 0; q < 4; q++)
            ((float4*)sS)[tid + q * 256] = sb4[t * (TJ * DD / 4) + tid + q * 256];
        __syncthreads();

        const float* arA = sA + iA * JR + t * TJ;
        const float* arB = sA + iB * JR + t * TJ;

        #pragma unroll 4
        for (int jj = 0; jj < TJ; jj += 2) {
            float2 avA = *(const float2*)(arA + jj);
            float2 avB = *(const float2*)(arB + jj);
            {
                ulonglong2 sv = *(const ulonglong2*)&sS[jj * DD + kq * 4];
                unsigned long long aA = bcast2(avA.x);
                unsigned long long aB = bcast2(avB.x);
                relu_mad4(accA0, accA1, sv.x, sv.y, tA.x, tA.y, aA);
                relu_mad4(accB0, accB1, sv.x, sv.y, tB.x, tB.y, aB);
            }
            {
                ulonglong2 sv = *(const ulonglong2*)&sS[(jj + 1) * DD + kq * 4];
                unsigned long long aA = bcast2(avA.y);
                unsigned long long aB = bcast2(avB.y);
                relu_mad4(accA0, accA1, sv.x, sv.y, tA.x, tA.y, aA);
                relu_mad4(accB0, accB1, sv.x, sv.y, tB.x, tB.y, aB);
            }
        }
        __syncthreads();
    }

    {
        ulonglong2 oA; oA.x = accA0; oA.y = accA1;
        ulonglong2 oB; oB.x = accB0; oB.y = accB1;
        size_t base = (((size_t)js * BB + b) * NN + i0) * DD;
        *(ulonglong2*)&g_v[base + (size_t)iA * DD + kq * 4] = oA;
        *(ulonglong2*)&g_v[base + (size_t)iB * DD + kq * 4] = oB;
    }
}

// ============ K3: sync-free outer-product: out = ES + (sum_js v) @ W2 + b2 ============
// grid 2048/ERM = 256 blocks, 256 threads.
// Thread (r = tid>>5, mp = tid&31): output pairs (2mp, 2mp+1) and (64+2mp, 64+2mp+1)
// of row r0+r. W2 read as packed pairs from g_W2p (LDG.128 along k, L1-broadcast).
__global__ void __launch_bounds__(256) k_epi(const float* __restrict__ ES,
                                             const float* __restrict__ b2,
                                             float* __restrict__ out_state)
{
    __shared__ float sV[ERM][DD];    // 4 KB folded v
    int tid = threadIdx.x;
    int r0  = blockIdx.x * ERM;

    const size_t PSTRIDE = (size_t)BB * NN * DD;
    // fold 4 partials: 8 rows x 128 = 256 float4, one per thread
    {
        int vrow = tid >> 5, kc = tid & 31;
        size_t off = ((size_t)(r0 + vrow)) * DD + kc * 4;
        float4 a = *(const float4*)&g_v[off];
        float4 c = *(const float4*)&g_v[off + PSTRIDE];
        float4 d = *(const float4*)&g_v[off + 2 * PSTRIDE];
        float4 e = *(const float4*)&g_v[off + 3 * PSTRIDE];
        a.x += c.x; a.y += c.y; a.z += c.z; a.w += c.w;
        d.x += e.x; d.y += e.y; d.z += e.z; d.w += e.w;
        a.x += d.x; a.y += d.y; a.z += d.z; a.w += d.w;
        *(float4*)&sV[vrow][kc * 4] = a;
    }
    __syncthreads();

    int r  = tid >> 5;
    int mp = tid & 31;

    const float2* w0 = (const float2*)g_W2p + (size_t)mp * DD;         // pair m=2mp
    const float2* w1 = (const float2*)g_W2p + (size_t)(32 + mp) * DD;  // pair m=64+2mp

    unsigned long long acc0 = 0ull, acc1 = 0ull;

    #pragma unroll 4
    for (int k = 0; k < DD; k += 4) {
        float4 v4 = *(const float4*)&sV[r][k];
        ulonglong2 a01 = *(const ulonglong2*)(w0 + k);
        ulonglong2 a23 = *(const ulonglong2*)(w0 + k + 2);
        ulonglong2 b01 = *(const ulonglong2*)(w1 + k);
        ulonglong2 b23 = *(const ulonglong2*)(w1 + k + 2);
        unsigned long long vx = bcast2(v4.x);
        unsigned long long vy = bcast2(v4.y);
        unsigned long long vz = bcast2(v4.z);
        unsigned long long vw = bcast2(v4.w);
        fma2acc(acc0, vx, a01.x); fma2acc(acc0, vy, a01.y);
        fma2acc(acc0, vz, a23.x); fma2acc(acc0, vw, a23.y);
        fma2acc(acc1, vx, b01.x); fma2acc(acc1, vy, b01.y);
        fma2acc(acc1, vz, b23.x); fma2acc(acc1, vw, b23.y);
    }

    size_t row = (size_t)(r0 + r);
    float2 es0 = *(const float2*)&ES[row * DD + 2 * mp];
    float2 es1 = *(const float2*)&ES[row * DD + 64 + 2 * mp];
    float2 bb0 = *(const float2*)&b2[2 * mp];
    float2 bb1 = *(const float2*)&b2[64 + 2 * mp];
    float2 p0  = unpack2(acc0);
    float2 p1  = unpack2(acc1);
    float2 o0, o1;
    o0.x = es0.x + p0.x + bb0.x;  o0.y = es0.y + p0.y + bb0.y;
    o1.x = es1.x + p1.x + bb1.x;  o1.y = es1.y + p1.y + bb1.y;
    *(float2*)&out_state[row * DD + 2 * mp]      = o0;
    *(float2*)&out_state[row * DD + 64 + 2 * mp] = o1;
}

// ---------------- launch ----------------
extern "C" void kernel_launch(void* const* d_in, const int* in_sizes, int n_in,
                              void* d_out, int out_size)
{
    const float* ES  = (const float*)d_in[0];
    const float* Wp  = (const float*)d_in[1];
    const float* bp  = (const float*)d_in[2];
    const float* EL  = (const float*)d_in[3];
    const float* W1  = (const float*)d_in[4];
    const float* b1  = (const float*)d_in[5];
    const float* W2  = (const float*)d_in[6];
    const float* b2  = (const float*)d_in[7];
    const float* UN  = (const float*)d_in[8];

    float* out_state = (float*)d_out;
    float* out_A     = (float*)d_out + (size_t)BB * NN * DD;

    k_combine<<<DD + 17, 256>>>(Wp, bp, W1, b1, W2);
    k_proj<<<dim3((BB * NN) / PBM, 256 / PBN), 256>>>(ES);
    k_main<<<dim3(NN / TI, BB, JS), 256>>>(EL, UN, out_A);
    k_epi<<<(BB * NN) / ERM, 256>>>(ES, b2, out_state);
}

// round 9
// speedup vs baseline: 1.4987x; 1.4987x over previous
#include <cuda_runtime.h>
#include <math.h>

#define BB 4
#define NN 512
#define DD 128
#define TAU_INV 2.0f
#define EPSF 1e-9f

#define TI 16            // i rows per k_main block
#define JS 4             // j splits
#define JR (NN/JS)       // 128 j's per block
#define TJ 32            // j tile staged in shared

// k_proj tiles
#define PBM 32
#define PBN 64
#define PBK 32
#define APAD 2

// k_epi
#define ERM 8            // rows per k_epi block (1 warp per row)

// ---------------- scratch ----------------
__device__ float g_sj[BB * NN * DD];          // (ES@Wp+bp)@W1_src + Bc_s
__device__ float g_ti[BB * NN * DD];          // (ES@Wp+bp)@W1_tgt + Bc_t (b1 folded)
__device__ float g_v [JS * BB * NN * DD];     // partial v per j-split (4 MB)
__device__ float g_Wc[DD * 256];              // combined weights [d][col], col<128 src
__device__ float g_Bc[256];                   // combined bias

// ---------------- packed f32x2 helpers ----------------
__device__ __forceinline__ void fma2acc(unsigned long long& acc,
                                        unsigned long long a, unsigned long long b) {
    asm("fma.rn.f32x2 %0, %1, %2, %0;" : "+l"(acc) : "l"(a), "l"(b));
}
__device__ __forceinline__ unsigned long long bcast2(float a) {
    unsigned long long r;
    asm("mov.b64 %0, {%1, %1};" : "=l"(r) : "f"(a));
    return r;
}
__device__ __forceinline__ float2 unpack2(unsigned long long v) {
    float2 r;
    asm("mov.b64 {%0, %1}, %2;" : "=f"(r.x), "=f"(r.y) : "l"(v));
    return r;
}
// acc += a * relu(s + t), 4 lanes (2 b64 packs)
__device__ __forceinline__ void relu_mad4(unsigned long long& acc0, unsigned long long& acc1,
                                          unsigned long long s0, unsigned long long s1,
                                          unsigned long long t0, unsigned long long t1,
                                          unsigned long long a2)
{
    asm("{\n\t"
        ".reg .b64 x0, x1;\n\t"
        ".reg .f32 l0, h0, l1, h1;\n\t"
        "add.rn.f32x2 x0, %2, %4;\n\t"
        "add.rn.f32x2 x1, %3, %5;\n\t"
        "mov.b64 {l0, h0}, x0;\n\t"
        "mov.b64 {l1, h1}, x1;\n\t"
        "max.f32 l0, l0, 0f00000000;\n\t"
        "max.f32 h0, h0, 0f00000000;\n\t"
        "max.f32 l1, l1, 0f00000000;\n\t"
        "max.f32 h1, h1, 0f00000000;\n\t"
        "mov.b64 x0, {l0, h0};\n\t"
        "mov.b64 x1, {l1, h1};\n\t"
        "fma.rn.f32x2 %0, x0, %6, %0;\n\t"
        "fma.rn.f32x2 %1, x1, %6, %1;\n\t"
        "}"
        : "+l"(acc0), "+l"(acc1)
        : "l"(s0), "l"(s1), "l"(t0), "l"(t1), "l"(a2));
}

// ============ K0: Wc = Wp @ [W1s|W1t];  Bc = bp @ [W1s|W1t] (+b1 tgt half) ============
__global__ void __launch_bounds__(256) k_combine(const float* __restrict__ Wp,
                                                 const float* __restrict__ bp,
                                                 const float* __restrict__ W1,
                                                 const float* __restrict__ b1)
{
    __shared__ float wp[DD];
    int col  = threadIdx.x;          // 0..255
    int d    = blockIdx.x;           // 0..128 (last block: biases)
    int half = col >> 7;
    int m    = col & 127;
    const float* base = W1 + (size_t)(half ? DD * DD : 0) + m;

    if (d < DD) {
        if (col < DD) wp[col] = Wp[d * DD + col];
        __syncthreads();
        float acc = 0.f;
        #pragma unroll 8
        for (int k = 0; k < DD; k++) acc += wp[k] * base[(size_t)k * DD];
        g_Wc[d * 256 + col] = acc;
    } else {
        float acc = half ? b1[m] : 0.f;
        #pragma unroll 8
        for (int k = 0; k < DD; k++) acc += bp[k] * base[(size_t)k * DD];
        g_Bc[col] = acc;
    }
}

// ============ K1: tiled GEMM: [s|t] = ES @ Wc + Bc ============
__global__ void __launch_bounds__(256) k_proj(const float* __restrict__ ES)
{
    __shared__ float sE[PBK][PBM + APAD];   // transposed: sE[k][row]
    __shared__ float sW[PBK][PBN];

    int tid = threadIdx.x;
    int tx  = tid & 15;
    int ty  = tid >> 4;
    int r0  = blockIdx.x * PBM;
    int c0  = blockIdx.y * PBN;

    int lrow = tid >> 3;
    int lk4  = tid & 7;
    int wk   = tid >> 4;
    int wc4  = tid & 15;

    float4 eA, wB[2];
    {
        eA    = *(const float4*)&ES[(size_t)(r0 + lrow) * DD + lk4 * 4];
        const float* wpg = g_Wc + c0;
        wB[0] = *(const float4*)&wpg[(wk     ) * 256 + wc4 * 4];
        wB[1] = *(const float4*)&wpg[(wk + 16) * 256 + wc4 * 4];
    }

    unsigned long long acc[2][2];
    acc[0][0] = acc[0][1] = acc[1][0] = acc[1][1] = 0ull;

    for (int kt = 0; kt < DD; kt += PBK) {
        if (kt) __syncthreads();
        sE[lk4 * 4 + 0][lrow] = eA.x;
        sE[lk4 * 4 + 1][lrow] = eA.y;
        sE[lk4 * 4 + 2][lrow] = eA.z;
        sE[lk4 * 4 + 3][lrow] = eA.w;
        *(float4*)&sW[wk][wc4 * 4]      = wB[0];
        *(float4*)&sW[wk + 16][wc4 * 4] = wB[1];
        __syncthreads();

        if (kt + PBK < DD) {
            eA    = *(const float4*)&ES[(size_t)(r0 + lrow) * DD + (kt + PBK) + lk4 * 4];
            const float* wpg = g_Wc + c0 + (size_t)(kt + PBK) * 256;
            wB[0] = *(const float4*)&wpg[(wk     ) * 256 + wc4 * 4];
            wB[1] = *(const float4*)&wpg[(wk + 16) * 256 + wc4 * 4];
        }

        #pragma unroll 8
        for (int k = 0; k < PBK; k++) {
            float2 e2 = *(const float2*)&sE[k][ty * 2];
            ulonglong2 w2 = *(const ulonglong2*)&sW[k][tx * 4];
            unsigned long long e0 = bcast2(e2.x);
            unsigned long long e1 = bcast2(e2.y);
            fma2acc(acc[0][0], e0, w2.x); fma2acc(acc[0][1], e0, w2.y);
            fma2acc(acc[1][0], e1, w2.x); fma2acc(acc[1][1], e1, w2.y);
        }
    }

    float4 bias = *(const float4*)&g_Bc[c0 + tx * 4];
    float* dst = (c0 < DD) ? g_sj : g_ti;
    int    mc  = (c0 < DD) ? c0 : (c0 - DD);
    #pragma unroll
    for (int r = 0; r < 2; r++) {
        int row = r0 + ty * 2 + r;
        float2 p0 = unpack2(acc[r][0]);
        float2 p1 = unpack2(acc[r][1]);
        float4 o;
        o.x = p0.x + bias.x; o.y = p0.y + bias.y;
        o.z = p1.x + bias.z; o.w = p1.y + bias.w;
        *(float4*)&dst[(size_t)row * DD + mc + tx * 4] = o;
    }
}

// ============ K2: fused gumbel-softmax + partial message aggregation ============
__global__ void __launch_bounds__(256, 4) k_main(const float* __restrict__ EL,
                                                 const float* __restrict__ UN,
                                                 float* __restrict__ out_A)
{
    __shared__ float sA[TI * JR];    // 8 KB
    __shared__ float sS[TJ * DD];    // 16 KB

    int tid = threadIdx.x;
    int b   = blockIdx.y;
    int i0  = blockIdx.x * TI;
    int js  = blockIdx.z;

    // phase A: gumbel-softmax rows i0..i0+15
    {
        int warp = tid >> 5, lane = tid & 31;
        #pragma unroll
        for (int rr = 0; rr < 2; rr++) {
            int r = warp * 2 + rr;
            int i = i0 + r;
            const float* elp = EL + (size_t)i * NN;
            const float* up  = UN + (size_t)i * NN;
            float xv[16];
            float mx = -1e30f;
            #pragma unroll
            for (int c = 0; c < 16; c++) {
                int j = c * 32 + lane;
                float inner = logf(up[j] + EPSF);
                float g = -__logf(-inner + EPSF);
                float x = (elp[j] + g) * TAU_INV;
                xv[c] = x;
                mx = fmaxf(mx, x);
            }
            #pragma unroll
            for (int o = 16; o > 0; o >>= 1) mx = fmaxf(mx, __shfl_xor_sync(0xffffffffu, mx, o));
            float s = 0.f;
            #pragma unroll
            for (int c = 0; c < 16; c++) { float e = __expf(xv[c] - mx); xv[c] = e; s += e; }
            #pragma unroll
            for (int o = 16; o > 0; o >>= 1) s += __shfl_xor_sync(0xffffffffu, s, o);
            float rinv = 1.0f / s;
            float* oA = out_A + ((size_t)b * NN + i) * NN;
            #pragma unroll
            for (int c = 0; c < 16; c++) {
                float a = xv[c] * rinv;
                if ((c >> 2) == js) sA[r * JR + (c & 3) * 32 + lane] = a;
                if (js == 0) oA[c * 32 + lane] = a;
            }
        }
    }
    __syncthreads();

    // phase B
    int kq = tid & 31;
    int ig = tid >> 5;
    int iA = ig * 2, iB = ig * 2 + 1;

    ulonglong2 tA = *(const ulonglong2*)&g_ti[((size_t)(b * NN + i0 + iA)) * DD + kq * 4];
    ulonglong2 tB = *(const ulonglong2*)&g_ti[((size_t)(b * NN + i0 + iB)) * DD + kq * 4];
    unsigned long long accA0 = 0ull, accA1 = 0ull, accB0 = 0ull, accB1 = 0ull;

    const float4* sb4 = (const float4*)(g_sj + ((size_t)b * NN + js * JR) * DD);

    #pragma unroll 1
    for (int t = 0; t < JR / TJ; t++) {
        #pragma unroll
        for (int q = 0; q < 4; q++)
            ((float4*)sS)[tid + q * 256] = sb4[t * (TJ * DD / 4) + tid + q * 256];
        __syncthreads();

        const float* arA = sA + iA * JR + t * TJ;
        const float* arB = sA + iB * JR + t * TJ;

        #pragma unroll 4
        for (int jj = 0; jj < TJ; jj += 2) {
            float2 avA = *(const float2*)(arA + jj);
            float2 avB = *(const float2*)(arB + jj);
            {
                ulonglong2 sv = *(const ulonglong2*)&sS[jj * DD + kq * 4];
                unsigned long long aA = bcast2(avA.x);
                unsigned long long aB = bcast2(avB.x);
                relu_mad4(accA0, accA1, sv.x, sv.y, tA.x, tA.y, aA);
                relu_mad4(accB0, accB1, sv.x, sv.y, tB.x, tB.y, aB);
            }
            {
                ulonglong2 sv = *(const ulonglong2*)&sS[(jj + 1) * DD + kq * 4];
                unsigned long long aA = bcast2(avA.y);
                unsigned long long aB = bcast2(avB.y);
                relu_mad4(accA0, accA1, sv.x, sv.y, tA.x, tA.y, aA);
                relu_mad4(accB0, accB1, sv.x, sv.y, tB.x, tB.y, aB);
            }
        }
        __syncthreads();
    }

    {
        ulonglong2 oA; oA.x = accA0; oA.y = accA1;
        ulonglong2 oB; oB.x = accB0; oB.y = accB1;
        size_t base = (((size_t)js * BB + b) * NN + i0) * DD;
        *(ulonglong2*)&g_v[base + (size_t)iA * DD + kq * 4] = oA;
        *(ulonglong2*)&g_v[base + (size_t)iB * DD + kq * 4] = oB;
    }
}

// ============ K3: sync-free coalesced epilogue: out = ES + (sum_js v) @ W2 + b2 =======
// grid 2048/ERM = 256 blocks, 256 threads = 8 warps.
// Warp w -> row r0+w. Lane l -> output columns 4l..4l+3.
// W2[k][4l..4l+3]: one coalesced 512B access per warp per k (minimum 4 lines).
// v[row][k]: conflict-free LDS broadcast.
__global__ void __launch_bounds__(256) k_epi(const float* __restrict__ ES,
                                             const float* __restrict__ W2,
                                             const float* __restrict__ b2,
                                             float* __restrict__ out_state)
{
    __shared__ float sV[ERM][DD];    // 4 KB folded v
    int tid = threadIdx.x;
    int r0  = blockIdx.x * ERM;

    const size_t PSTRIDE = (size_t)BB * NN * DD;
    // fold 4 partials: 8 rows x 128 = 256 float4, one per thread
    {
        int vrow = tid >> 5, kc = tid & 31;
        size_t off = ((size_t)(r0 + vrow)) * DD + kc * 4;
        float4 a = *(const float4*)&g_v[off];
        float4 c = *(const float4*)&g_v[off + PSTRIDE];
        float4 d = *(const float4*)&g_v[off + 2 * PSTRIDE];
        float4 e = *(const float4*)&g_v[off + 3 * PSTRIDE];
        a.x += c.x; a.y += c.y; a.z += c.z; a.w += c.w;
        d.x += e.x; d.y += e.y; d.z += e.z; d.w += e.w;
        a.x += d.x; a.y += d.y; a.z += d.z; a.w += d.w;
        *(float4*)&sV[vrow][kc * 4] = a;
    }
    __syncthreads();

    int w = tid >> 5;        // warp -> row
    int l = tid & 31;        // lane -> cols 4l..4l+3

    unsigned long long acc0 = 0ull, acc1 = 0ull;

    #pragma unroll 8
    for (int k = 0; k < DD; k++) {
        ulonglong2 w2 = *(const ulonglong2*)&W2[(size_t)k * DD + 4 * l];
        unsigned long long vb = bcast2(sV[w][k]);
        fma2acc(acc0, vb, w2.x);
        fma2acc(acc1, vb, w2.y);
    }

    size_t row = (size_t)(r0 + w);
    float4 es = *(const float4*)&ES[row * DD + 4 * l];
    float4 bb = *(const float4*)&b2[4 * l];
    float2 p0 = unpack2(acc0);
    float2 p1 = unpack2(acc1);
    float4 o;
    o.x = es.x + p0.x + bb.x;
    o.y = es.y + p0.y + bb.y;
    o.z = es.z + p1.x + bb.z;
    o.w = es.w + p1.y + bb.w;
    *(float4*)&out_state[row * DD + 4 * l] = o;
}

// ---------------- launch ----------------
extern "C" void kernel_launch(void* const* d_in, const int* in_sizes, int n_in,
                              void* d_out, int out_size)
{
    const float* ES  = (const float*)d_in[0];
    const float* Wp  = (const float*)d_in[1];
    const float* bp  = (const float*)d_in[2];
    const float* EL  = (const float*)d_in[3];
    const float* W1  = (const float*)d_in[4];
    const float* b1  = (const float*)d_in[5];
    const float* W2  = (const float*)d_in[6];
    const float* b2  = (const float*)d_in[7];
    const float* UN  = (const float*)d_in[8];

    float* out_state = (float*)d_out;
    float* out_A     = (float*)d_out + (size_t)BB * NN * DD;

    k_combine<<<DD + 1, 256>>>(Wp, bp, W1, b1);
    k_proj<<<dim3((BB * NN) / PBM, 256 / PBN), 256>>>(ES);
    k_main<<<dim3(NN / TI, BB, JS), 256>>>(EL, UN, out_A);
    k_epi<<<(BB * NN) / ERM, 256>>>(ES, W2, b2, out_state);
}

// round 10
// speedup vs baseline: 1.7003x; 1.1345x over previous
#include <cuda_runtime.h>
#include <math.h>

#define BB 4
#define NN 512
#define DD 128
#define TAU_INV 2.0f
#define EPSF 1e-9f

#define TI 16            // i rows per k_main block
#define JS 2             // j splits
#define JR (NN/JS)       // 256 j's per block
#define TJ 32            // j tile staged in shared

// k_proj tiles
#define PBM 32
#define PBN 64
#define PBK 32
#define APAD 2

// ---------------- scratch ----------------
__device__ float g_sj[BB * NN * DD];          // (ES@Wp+bp)@W1_src + Bc_s
__device__ float g_ti[BB * NN * DD];          // (ES@Wp+bp)@W1_tgt + Bc_t (b1 folded)
__device__ float g_Wc[DD * 256];              // combined weights [d][col], col<128 src
__device__ float g_Bc[256];                   // combined bias

// ---------------- packed f32x2 helpers ----------------
__device__ __forceinline__ void fma2acc(unsigned long long& acc,
                                        unsigned long long a, unsigned long long b) {
    asm("fma.rn.f32x2 %0, %1, %2, %0;" : "+l"(acc) : "l"(a), "l"(b));
}
__device__ __forceinline__ unsigned long long bcast2(float a) {
    unsigned long long r;
    asm("mov.b64 %0, {%1, %1};" : "=l"(r) : "f"(a));
    return r;
}
__device__ __forceinline__ float2 unpack2(unsigned long long v) {
    float2 r;
    asm("mov.b64 {%0, %1}, %2;" : "=f"(r.x), "=f"(r.y) : "l"(v));
    return r;
}
// acc += a * relu(s + t), 4 lanes (2 b64 packs)
__device__ __forceinline__ void relu_mad4(unsigned long long& acc0, unsigned long long& acc1,
                                          unsigned long long s0, unsigned long long s1,
                                          unsigned long long t0, unsigned long long t1,
                                          unsigned long long a2)
{
    asm("{\n\t"
        ".reg .b64 x0, x1;\n\t"
        ".reg .f32 l0, h0, l1, h1;\n\t"
        "add.rn.f32x2 x0, %2, %4;\n\t"
        "add.rn.f32x2 x1, %3, %5;\n\t"
        "mov.b64 {l0, h0}, x0;\n\t"
        "mov.b64 {l1, h1}, x1;\n\t"
        "max.f32 l0, l0, 0f00000000;\n\t"
        "max.f32 h0, h0, 0f00000000;\n\t"
        "max.f32 l1, l1, 0f00000000;\n\t"
        "max.f32 h1, h1, 0f00000000;\n\t"
        "mov.b64 x0, {l0, h0};\n\t"
        "mov.b64 x1, {l1, h1};\n\t"
        "fma.rn.f32x2 %0, x0, %6, %0;\n\t"
        "fma.rn.f32x2 %1, x1, %6, %1;\n\t"
        "}"
        : "+l"(acc0), "+l"(acc1)
        : "l"(s0), "l"(s1), "l"(t0), "l"(t1), "l"(a2));
}

// ============ K0: Wc = Wp @ [W1s|W1t];  Bc = bp @ [W1s|W1t] (+b1 tgt half) ============
__global__ void __launch_bounds__(256) k_combine(const float* __restrict__ Wp,
                                                 const float* __restrict__ bp,
                                                 const float* __restrict__ W1,
                                                 const float* __restrict__ b1)
{
    __shared__ float wp[DD];
    int col  = threadIdx.x;          // 0..255
    int d    = blockIdx.x;           // 0..128 (last block: biases)
    int half = col >> 7;
    int m    = col & 127;
    const float* base = W1 + (size_t)(half ? DD * DD : 0) + m;

    if (d < DD) {
        if (col < DD) wp[col] = Wp[d * DD + col];
        __syncthreads();
        float acc = 0.f;
        #pragma unroll 8
        for (int k = 0; k < DD; k++) acc += wp[k] * base[(size_t)k * DD];
        g_Wc[d * 256 + col] = acc;
    } else {
        float acc = half ? b1[m] : 0.f;
        #pragma unroll 8
        for (int k = 0; k < DD; k++) acc += bp[k] * base[(size_t)k * DD];
        g_Bc[col] = acc;
    }
}

// ============ K1: tiled GEMM: [s|t] = ES @ Wc + Bc; by==0 blocks also init out ========
__global__ void __launch_bounds__(256) k_proj(const float* __restrict__ ES,
                                              const float* __restrict__ b2,
                                              float* __restrict__ out_state)
{
    __shared__ float sE[PBK][PBM + APAD];   // transposed: sE[k][row]
    __shared__ float sW[PBK][PBN];

    int tid = threadIdx.x;
    int tx  = tid & 15;
    int ty  = tid >> 4;
    int r0  = blockIdx.x * PBM;
    int c0  = blockIdx.y * PBN;

    int lrow = tid >> 3;
    int lk4  = tid & 7;
    int wk   = tid >> 4;
    int wc4  = tid & 15;

    float4 eA, wB[2];
    {
        eA    = *(const float4*)&ES[(size_t)(r0 + lrow) * DD + lk4 * 4];
        const float* wpg = g_Wc + c0;
        wB[0] = *(const float4*)&wpg[(wk     ) * 256 + wc4 * 4];
        wB[1] = *(const float4*)&wpg[(wk + 16) * 256 + wc4 * 4];
    }

    unsigned long long acc[2][2];
    acc[0][0] = acc[0][1] = acc[1][0] = acc[1][1] = 0ull;

    for (int kt = 0; kt < DD; kt += PBK) {
        if (kt) __syncthreads();
        sE[lk4 * 4 + 0][lrow] = eA.x;
        sE[lk4 * 4 + 1][lrow] = eA.y;
        sE[lk4 * 4 + 2][lrow] = eA.z;
        sE[lk4 * 4 + 3][lrow] = eA.w;
        *(float4*)&sW[wk][wc4 * 4]      = wB[0];
        *(float4*)&sW[wk + 16][wc4 * 4] = wB[1];
        __syncthreads();

        if (kt + PBK < DD) {
            eA    = *(const float4*)&ES[(size_t)(r0 + lrow) * DD + (kt + PBK) + lk4 * 4];
            const float* wpg = g_Wc + c0 + (size_t)(kt + PBK) * 256;
            wB[0] = *(const float4*)&wpg[(wk     ) * 256 + wc4 * 4];
            wB[1] = *(const float4*)&wpg[(wk + 16) * 256 + wc4 * 4];
        }

        #pragma unroll 8
        for (int k = 0; k < PBK; k++) {
            float2 e2 = *(const float2*)&sE[k][ty * 2];
            ulonglong2 w2 = *(const ulonglong2*)&sW[k][tx * 4];
            unsigned long long e0 = bcast2(e2.x);
            unsigned long long e1 = bcast2(e2.y);
            fma2acc(acc[0][0], e0, w2.x); fma2acc(acc[0][1], e0, w2.y);
            fma2acc(acc[1][0], e1, w2.x); fma2acc(acc[1][1], e1, w2.y);
        }
    }

    float4 bias = *(const float4*)&g_Bc[c0 + tx * 4];
    float* dst = (c0 < DD) ? g_sj : g_ti;
    int    mc  = (c0 < DD) ? c0 : (c0 - DD);
    #pragma unroll
    for (int r = 0; r < 2; r++) {
        int row = r0 + ty * 2 + r;
        float2 p0 = unpack2(acc[r][0]);
        float2 p1 = unpack2(acc[r][1]);
        float4 o;
        o.x = p0.x + bias.x; o.y = p0.y + bias.y;
        o.z = p1.x + bias.z; o.w = p1.y + bias.w;
        *(float4*)&dst[(size_t)row * DD + mc + tx * 4] = o;
    }

    // init out_state = ES + b2 for this block's 32 rows (one colblock does it)
    if (blockIdx.y == 0) {
        #pragma unroll
        for (int q = 0; q < 4; q++) {
            int idx = tid + q * 256;         // 0..1023 float4's
            int row = r0 + (idx >> 5);
            int c4  = idx & 31;
            float4 es = *(const float4*)&ES[(size_t)row * DD + c4 * 4];
            float4 bb = *(const float4*)&b2[c4 * 4];
            float4 o;
            o.x = es.x + bb.x; o.y = es.y + bb.y;
            o.z = es.z + bb.z; o.w = es.w + bb.w;
            *(float4*)&out_state[(size_t)row * DD + c4 * 4] = o;
        }
    }
}

// ============ K2: fused softmax + aggregation + partial epilogue (atomics) ============
// grid (32, 4, 2), 256 threads.
__global__ void __launch_bounds__(256, 4) k_main(const float* __restrict__ EL,
                                                 const float* __restrict__ UN,
                                                 const float* __restrict__ W2,
                                                 float* __restrict__ out_A,
                                                 float* __restrict__ out_state)
{
    __shared__ float sA[TI * JR];    // 16 KB : A slice for this j-split
    __shared__ float sS[TJ * DD];    // 16 KB : s tile; overlaid by sV (8 KB) in phase C

    int tid = threadIdx.x;
    int b   = blockIdx.y;
    int i0  = blockIdx.x * TI;
    int js  = blockIdx.z;

    // -------- phase A: gumbel-softmax rows i0..i0+15, keep js half --------
    {
        int warp = tid >> 5, lane = tid & 31;
        #pragma unroll
        for (int rr = 0; rr < 2; rr++) {
            int r = warp * 2 + rr;
            int i = i0 + r;
            const float* elp = EL + (size_t)i * NN;
            const float* up  = UN + (size_t)i * NN;
            float xv[16];
            float mx = -1e30f;
            #pragma unroll
            for (int c = 0; c < 16; c++) {
                int j = c * 32 + lane;
                float inner = logf(up[j] + EPSF);
                float g = -__logf(-inner + EPSF);
                float x = (elp[j] + g) * TAU_INV;
                xv[c] = x;
                mx = fmaxf(mx, x);
            }
            #pragma unroll
            for (int o = 16; o > 0; o >>= 1) mx = fmaxf(mx, __shfl_xor_sync(0xffffffffu, mx, o));
            float s = 0.f;
            #pragma unroll
            for (int c = 0; c < 16; c++) { float e = __expf(xv[c] - mx); xv[c] = e; s += e; }
            #pragma unroll
            for (int o = 16; o > 0; o >>= 1) s += __shfl_xor_sync(0xffffffffu, s, o);
            float rinv = 1.0f / s;
            float* oA = out_A + ((size_t)b * NN + i) * NN;
            #pragma unroll
            for (int c = 0; c < 16; c++) {
                float a = xv[c] * rinv;
                if ((c >> 3) == js) sA[r * JR + (c & 7) * 32 + lane] = a;
                if (js == 0) oA[c * 32 + lane] = a;
            }
        }
    }
    __syncthreads();

    // -------- phase B: v_partial[i,k] = sum_{j in half} A[i,j]*relu(t_i[k]+s_j[k]) ----
    int kq = tid & 31;       // k quad: k = kq*4
    int ig = tid >> 5;       // warp id 0..7 -> i rows ig*2, ig*2+1
    int iA = ig * 2, iB = ig * 2 + 1;

    ulonglong2 tA = *(const ulonglong2*)&g_ti[((size_t)(b * NN + i0 + iA)) * DD + kq * 4];
    ulonglong2 tB = *(const ulonglong2*)&g_ti[((size_t)(b * NN + i0 + iB)) * DD + kq * 4];
    unsigned long long accA0 = 0ull, accA1 = 0ull, accB0 = 0ull, accB1 = 0ull;

    const float4* sb4 = (const float4*)(g_sj + ((size_t)b * NN + js * JR) * DD);

    #pragma unroll 1
    for (int t = 0; t < JR / TJ; t++) {
        #pragma unroll
        for (int q = 0; q < 4; q++)
            ((float4*)sS)[tid + q * 256] = sb4[t * (TJ * DD / 4) + tid + q * 256];
        __syncthreads();

        const float* arA = sA + iA * JR + t * TJ;
        const float* arB = sA + iB * JR + t * TJ;

        #pragma unroll 4
        for (int jj = 0; jj < TJ; jj += 2) {
            float2 avA = *(const float2*)(arA + jj);
            float2 avB = *(const float2*)(arB + jj);
            {
                ulonglong2 sv = *(const ulonglong2*)&sS[jj * DD + kq * 4];
                unsigned long long aA = bcast2(avA.x);
                unsigned long long aB = bcast2(avB.x);
                relu_mad4(accA0, accA1, sv.x, sv.y, tA.x, tA.y, aA);
                relu_mad4(accB0, accB1, sv.x, sv.y, tB.x, tB.y, aB);
            }
            {
                ulonglong2 sv = *(const ulonglong2*)&sS[(jj + 1) * DD + kq * 4];
                unsigned long long aA = bcast2(avA.y);
                unsigned long long aB = bcast2(avB.y);
                relu_mad4(accA0, accA1, sv.x, sv.y, tA.x, tA.y, aA);
                relu_mad4(accB0, accB1, sv.x, sv.y, tB.x, tB.y, aB);
            }
        }
        __syncthreads();
    }

    // -------- phase C: out += v_partial @ W2 (atomic; order-independent up to fp) ----
    float* sV = sS;          // overlay: 16 rows x 128 k = 8 KB
    {
        ulonglong2 oA; oA.x = accA0; oA.y = accA1;
        ulonglong2 oB; oB.x = accB0; oB.y = accB1;
        *(ulonglong2*)&sV[iA * DD + kq * 4] = oA;
        *(ulonglong2*)&sV[iB * DD + kq * 4] = oB;
    }
    __syncthreads();

    {
        int cp = tid & 63;           // col pair: cols 2cp, 2cp+1
        int rg = tid >> 6;           // 0..3 -> rows rg*4 .. rg*4+3
        unsigned long long o0 = 0ull, o1 = 0ull, o2 = 0ull, o3 = 0ull;

        #pragma unroll 4
        for (int k = 0; k < DD; k++) {
            unsigned long long w2 = *(const unsigned long long*)&W2[(size_t)k * DD + 2 * cp];
            fma2acc(o0, bcast2(sV[(rg * 4 + 0) * DD + k]), w2);
            fma2acc(o1, bcast2(sV[(rg * 4 + 1) * DD + k]), w2);
            fma2acc(o2, bcast2(sV[(rg * 4 + 2) * DD + k]), w2);
            fma2acc(o3, bcast2(sV[(rg * 4 + 3) * DD + k]), w2);
        }

        size_t base = ((size_t)b * NN + i0 + rg * 4) * DD + 2 * cp;
        float2 q0 = unpack2(o0);
        float2 q1 = unpack2(o1);
        float2 q2 = unpack2(o2);
        float2 q3 = unpack2(o3);
        atomicAdd(&out_state[base + 0 * DD + 0], q0.x);
        atomicAdd(&out_state[base + 0 * DD + 1], q0.y);
        atomicAdd(&out_state[base + 1 * DD + 0], q1.x);
        atomicAdd(&out_state[base + 1 * DD + 1], q1.y);
        atomicAdd(&out_state[base + 2 * DD + 0], q2.x);
        atomicAdd(&out_state[base + 2 * DD + 1], q2.y);
        atomicAdd(&out_state[base + 3 * DD + 0], q3.x);
        atomicAdd(&out_state[base + 3 * DD + 1], q3.y);
    }
}

// ---------------- launch ----------------
extern "C" void kernel_launch(void* const* d_in, const int* in_sizes, int n_in,
                              void* d_out, int out_size)
{
    const float* ES  = (const float*)d_in[0];
    const float* Wp  = (const float*)d_in[1];
    const float* bp  = (const float*)d_in[2];
    const float* EL  = (const float*)d_in[3];
    const float* W1  = (const float*)d_in[4];
    const float* b1  = (const float*)d_in[5];
    const float* W2  = (const float*)d_in[6];
    const float* b2  = (const float*)d_in[7];
    const float* UN  = (const float*)d_in[8];

    float* out_state = (float*)d_out;
    float* out_A     = (float*)d_out + (size_t)BB * NN * DD;

    k_combine<<<DD + 1, 256>>>(Wp, bp, W1, b1);
    k_proj<<<dim3((BB * NN) / PBM, 256 / PBN), 256>>>(ES, b2, out_state);
    k_main<<<dim3(NN / TI, BB, JS), 256>>>(EL, UN, W2, out_A, out_state);
}